// round 9
// baseline (speedup 1.0000x reference)
#include <cuda_runtime.h>
#include <cuda_fp16.h>

#define WPB 4
#define THREADS (WPB * 32)
#define R 8
#define NPAIR (R / 2)

#define EMB_ELEMS (7424 * 128)
__device__ __half g_emb_h[EMB_ELEMS];   // fp16 repacked embedding table (1.9 MB)

__global__ void cvt_emb_kernel(const float* __restrict__ emb, int n)
{
    int i = blockIdx.x * blockDim.x + threadIdx.x;
    if (i < n) g_emb_h[i] = __float2half(emb[i]);
}

// Packed 2-wide fp32 ops (Blackwell f32x2 pipe; PTX-only).
__device__ __forceinline__ float2 ffma2(float2 a, float2 b, float2 c)
{
    float2 d;
    asm("{\n\t.reg .b64 ra,rb,rc,rd;\n\t"
        "mov.b64 ra,{%2,%3};\n\tmov.b64 rb,{%4,%5};\n\tmov.b64 rc,{%6,%7};\n\t"
        "fma.rn.f32x2 rd, ra, rb, rc;\n\t"
        "mov.b64 {%0,%1}, rd;\n\t}"
        : "=f"(d.x), "=f"(d.y)
        : "f"(a.x), "f"(a.y), "f"(b.x), "f"(b.y), "f"(c.x), "f"(c.y));
    return d;
}
__device__ __forceinline__ float2 fadd2(float2 a, float2 b)
{
    float2 d;
    asm("{\n\t.reg .b64 ra,rb,rd;\n\t"
        "mov.b64 ra,{%2,%3};\n\tmov.b64 rb,{%4,%5};\n\t"
        "add.rn.f32x2 rd, ra, rb;\n\t"
        "mov.b64 {%0,%1}, rd;\n\t}"
        : "=f"(d.x), "=f"(d.y)
        : "f"(a.x), "f"(a.y), "f"(b.x), "f"(b.y));
    return d;
}

__global__ __launch_bounds__(THREADS)
void silk_nnue_kernel(const int*   __restrict__ x,
                      const float* __restrict__ W2,
                      const float* __restrict__ b2,
                      const float* __restrict__ W3,
                      const float* __restrict__ b3,
                      const float* __restrict__ W4,
                      float*       __restrict__ out,
                      int nrows)
{
    // fp32 weights, padded stride 132/68 floats => conflict-free LDS.128 sweeps.
    __shared__ float  sW2[32 * 132];
    __shared__ float  sW3[32 * 68];
    __shared__ float  sb2[32], sb3[32], sW4[64];
    // Per-warp pair-interleaved fp32 activations: (q,k) = {row2q[k], row2q+1[k]}
    __shared__ float2 sh[WPB][NPAIR * 128];

    const int tid = threadIdx.x;

    for (int i = tid; i < 32 * 128; i += THREADS)
        sW2[(i >> 7) * 132 + (i & 127)] = W2[i];
    for (int i = tid; i < 32 * 64; i += THREADS)
        sW3[(i >> 6) * 68 + (i & 63)] = W3[i];
    if (tid < 32)       sb2[tid]      = b2[tid];
    else if (tid < 64)  sb3[tid - 32] = b3[tid - 32];
    if (tid < 64)       sW4[tid]      = W4[tid];
    __syncthreads();

    const int lane = tid & 31;
    const int w    = tid >> 5;

    const float bias2 = sb2[lane];
    const float bias3 = sb3[lane];
    const float2 w4lo2 = make_float2(sW4[lane],      sW4[lane]);
    const float2 w4hi2 = make_float2(sW4[lane + 32], sW4[lane + 32]);

    float2* shw = sh[w];
    // Per-lane base pointer (loop-invariant). Lane owns halves
    // {2l, 2l+1} (first 128B line) and {64+2l, 64+2l+1} (second line).
    const unsigned* __restrict__ embu_lane = ((const unsigned*)g_emb_h) + lane;
    const float4* wrow2 = (const float4*)(sW2 + lane * 132);
    const float4* wrow3 = (const float4*)(sW3 + lane * 68);

    const int gwarp = blockIdx.x * WPB + w;
    const int row0  = gwarp * R;
    if (row0 >= nrows) return;
    const bool full = (row0 + R <= nrows);

    int xi[R];
    #pragma unroll
    for (int r = 0; r < R; ++r) {
        int row = row0 + r;
        xi[r] = (full || row < nrows) ? x[row * 32 + lane] : 0;
    }

    // ---- Gather-sum. ONE pointer per (j,r); second load at +128B so ptxas
    //      emits LDG [Rn] / LDG [Rn+0x80] off a shared base register.
    //      Two 1-wavefront loads (cross-LDG 1.0 cyc/wf) instead of one
    //      LDG.64 with 2 within-LDG replay wavefronts (2 x 2.07).
    float2 acc01[R], acc23[R];
    #pragma unroll
    for (int r = 0; r < R; ++r) {
        acc01[r] = make_float2(0.f, 0.f);
        acc23[r] = make_float2(0.f, 0.f);
    }

    for (int j = 0; j < 29; ++j) {
        #pragma unroll
        for (int r = 0; r < R; ++r) {
            int idx = __shfl_sync(0xffffffffu, xi[r], j);
            const unsigned* p = embu_lane + idx * 64;   // one IMAD.WIDE
            unsigned v0 = __ldg(p);                     // [Rn]
            unsigned v1 = __ldg(p + 32);                // [Rn + 0x80]
            acc01[r] = fadd2(acc01[r], __half22float2(*(const __half2*)&v0));
            acc23[r] = fadd2(acc23[r], __half22float2(*(const __half2*)&v1));
        }
    }

    // ReLU + pair-interleaved store at absolute k positions (two STS.128, conflict-free).
    #pragma unroll
    for (int q = 0; q < NPAIR; ++q) {
        const int r0 = 2 * q, r1 = 2 * q + 1;
        float4 s0 = make_float4(fmaxf(acc01[r0].x, 0.f), fmaxf(acc01[r1].x, 0.f),
                                fmaxf(acc01[r0].y, 0.f), fmaxf(acc01[r1].y, 0.f));
        float4 s1 = make_float4(fmaxf(acc23[r0].x, 0.f), fmaxf(acc23[r1].x, 0.f),
                                fmaxf(acc23[r0].y, 0.f), fmaxf(acc23[r1].y, 0.f));
        *(float4*)(shw + q * 128 + 2 * lane)      = s0;   // k = 2l, 2l+1
        *(float4*)(shw + q * 128 + 64 + 2 * lane) = s1;   // k = 64+2l, 64+2l+1
    }
    __syncwarp();

    // ---- Layer 2: packed over row-pairs; weights amortized over 8 rows ----
    float2 h2p[NPAIR];
    #pragma unroll
    for (int q = 0; q < NPAIR; ++q) h2p[q] = make_float2(bias2, bias2);

    #pragma unroll 8
    for (int c = 0; c < 32; ++c) {              // k = 4c..4c+3
        float4 wv = wrow2[c];
        float2 wxx = make_float2(wv.x, wv.x);
        float2 wyy = make_float2(wv.y, wv.y);
        float2 wzz = make_float2(wv.z, wv.z);
        float2 www = make_float2(wv.w, wv.w);
        #pragma unroll
        for (int q = 0; q < NPAIR; ++q) {
            const float4* hq = (const float4*)(shw + q * 128);
            float4 p0 = hq[2 * c];              // {k=4c, 4c+1} broadcast
            float4 p1 = hq[2 * c + 1];          // {k=4c+2, 4c+3}
            h2p[q] = ffma2(wxx, make_float2(p0.x, p0.y), h2p[q]);
            h2p[q] = ffma2(wyy, make_float2(p0.z, p0.w), h2p[q]);
            h2p[q] = ffma2(wzz, make_float2(p1.x, p1.y), h2p[q]);
            h2p[q] = ffma2(www, make_float2(p1.z, p1.w), h2p[q]);
        }
    }

    // ---- CReLU -> pair-interleaved a, reuse sh region ----
    __syncwarp();
    #pragma unroll
    for (int q = 0; q < NPAIR; ++q) {
        float2 alo = make_float2(fmaxf(h2p[q].x, 0.f), fmaxf(h2p[q].y, 0.f));
        float2 ahi = make_float2(fmaxf(-h2p[q].x, 0.f), fmaxf(-h2p[q].y, 0.f));
        shw[q * 64 + lane]      = alo;
        shw[q * 64 + lane + 32] = ahi;
    }
    __syncwarp();

    // ---- Layer 3 ----
    float2 h3p[NPAIR];
    #pragma unroll
    for (int q = 0; q < NPAIR; ++q) h3p[q] = make_float2(bias3, bias3);

    #pragma unroll 4
    for (int c = 0; c < 16; ++c) {
        float4 wv = wrow3[c];
        float2 wxx = make_float2(wv.x, wv.x);
        float2 wyy = make_float2(wv.y, wv.y);
        float2 wzz = make_float2(wv.z, wv.z);
        float2 www = make_float2(wv.w, wv.w);
        #pragma unroll
        for (int q = 0; q < NPAIR; ++q) {
            const float4* aq = (const float4*)(shw + q * 64);
            float4 p0 = aq[2 * c];
            float4 p1 = aq[2 * c + 1];
            h3p[q] = ffma2(wxx, make_float2(p0.x, p0.y), h3p[q]);
            h3p[q] = ffma2(wyy, make_float2(p0.z, p0.w), h3p[q]);
            h3p[q] = ffma2(wzz, make_float2(p1.x, p1.y), h3p[q]);
            h3p[q] = ffma2(www, make_float2(p1.z, p1.w), h3p[q]);
        }
    }

    // ---- Layer 4 + packed warp reduction ----
    float2 part[NPAIR];
    #pragma unroll
    for (int q = 0; q < NPAIR; ++q) {
        float2 blo = make_float2(fmaxf(h3p[q].x, 0.f), fmaxf(h3p[q].y, 0.f));
        float2 bhi = make_float2(fmaxf(-h3p[q].x, 0.f), fmaxf(-h3p[q].y, 0.f));
        float2 p = ffma2(w4hi2, bhi, make_float2(0.f, 0.f));
        p = ffma2(w4lo2, blo, p);
        #pragma unroll
        for (int off = 16; off; off >>= 1) {
            float2 o;
            o.x = __shfl_xor_sync(0xffffffffu, p.x, off);
            o.y = __shfl_xor_sync(0xffffffffu, p.y, off);
            p = fadd2(p, o);
        }
        part[q] = p;
    }

    if (lane == 0) {
        if (full) {
            *(float4*)(out + row0) =
                make_float4(part[0].x, part[0].y, part[1].x, part[1].y);
            *(float4*)(out + row0 + 4) =
                make_float4(part[2].x, part[2].y, part[3].x, part[3].y);
        } else {
            float pr[R] = {part[0].x, part[0].y, part[1].x, part[1].y,
                           part[2].x, part[2].y, part[3].x, part[3].y};
            for (int r = 0; r < R && row0 + r < nrows; ++r) out[row0 + r] = pr[r];
        }
    }
}

extern "C" void kernel_launch(void* const* d_in, const int* in_sizes, int n_in,
                              void* d_out, int out_size)
{
    const int*   x   = (const int*)  d_in[0];
    const float* emb = (const float*)d_in[1];
    const float* W2  = (const float*)d_in[2];
    const float* b2  = (const float*)d_in[3];
    const float* W3  = (const float*)d_in[4];
    const float* b3  = (const float*)d_in[5];
    const float* W4  = (const float*)d_in[6];
    float* out = (float*)d_out;

    int nemb  = in_sizes[1];
    int nrows = in_sizes[0] / 32;

    cvt_emb_kernel<<<(nemb + 511) / 512, 512>>>(emb, nemb);

    int ngroups = (nrows + R - 1) / R;
    int nblocks = (ngroups + WPB - 1) / WPB;
    silk_nnue_kernel<<<nblocks, THREADS>>>(x, W2, b2, W3, b3, W4, out, nrows);
}

// round 10
// speedup vs baseline: 2.1065x; 2.1065x over previous
#include <cuda_runtime.h>
#include <cuda_fp16.h>

#define WPB 4
#define THREADS (WPB * 32)
#define R 8
#define NPAIR (R / 2)

#define EMB_ELEMS (7424 * 128)
__device__ __half g_emb_h[EMB_ELEMS];   // fp16 repacked embedding table (1.9 MB)

__global__ void cvt_emb_kernel(const float* __restrict__ emb, int n)
{
    int i = blockIdx.x * blockDim.x + threadIdx.x;
    if (i < n) g_emb_h[i] = __float2half(emb[i]);
}

// Packed 2-wide fp32 ops (Blackwell f32x2 pipe; PTX-only).
__device__ __forceinline__ float2 ffma2(float2 a, float2 b, float2 c)
{
    float2 d;
    asm("{\n\t.reg .b64 ra,rb,rc,rd;\n\t"
        "mov.b64 ra,{%2,%3};\n\tmov.b64 rb,{%4,%5};\n\tmov.b64 rc,{%6,%7};\n\t"
        "fma.rn.f32x2 rd, ra, rb, rc;\n\t"
        "mov.b64 {%0,%1}, rd;\n\t}"
        : "=f"(d.x), "=f"(d.y)
        : "f"(a.x), "f"(a.y), "f"(b.x), "f"(b.y), "f"(c.x), "f"(c.y));
    return d;
}
__device__ __forceinline__ float2 fadd2(float2 a, float2 b)
{
    float2 d;
    asm("{\n\t.reg .b64 ra,rb,rd;\n\t"
        "mov.b64 ra,{%2,%3};\n\tmov.b64 rb,{%4,%5};\n\t"
        "add.rn.f32x2 rd, ra, rb;\n\t"
        "mov.b64 {%0,%1}, rd;\n\t}"
        : "=f"(d.x), "=f"(d.y)
        : "f"(a.x), "f"(a.y), "f"(b.x), "f"(b.y));
    return d;
}

__global__ __launch_bounds__(THREADS, 7)   // cap regs ~73 -> 28 warps/SM
void silk_nnue_kernel(const int*   __restrict__ x,
                      const float* __restrict__ W2,
                      const float* __restrict__ b2,
                      const float* __restrict__ W3,
                      const float* __restrict__ b3,
                      const float* __restrict__ W4,
                      float*       __restrict__ out,
                      int nrows)
{
    // fp32 weights, padded stride 132/68 floats => conflict-free LDS.128 sweeps.
    __shared__ float  sW2[32 * 132];
    __shared__ float  sW3[32 * 68];
    __shared__ float  sb2[32], sb3[32], sW4[64];
    // Per-warp pair-interleaved fp32 activations: (q,k) = {row2q[k], row2q+1[k]}
    __shared__ float2 sh[WPB][NPAIR * 128];

    const int tid = threadIdx.x;

    for (int i = tid; i < 32 * 128; i += THREADS)
        sW2[(i >> 7) * 132 + (i & 127)] = W2[i];
    for (int i = tid; i < 32 * 64; i += THREADS)
        sW3[(i >> 6) * 68 + (i & 63)] = W3[i];
    if (tid < 32)       sb2[tid]      = b2[tid];
    else if (tid < 64)  sb3[tid - 32] = b3[tid - 32];
    if (tid < 64)       sW4[tid]      = W4[tid];
    __syncthreads();

    const int lane = tid & 31;
    const int w    = tid >> 5;

    const float bias2 = sb2[lane];
    const float bias3 = sb3[lane];
    const float2 w4lo2 = make_float2(sW4[lane],      sW4[lane]);
    const float2 w4hi2 = make_float2(sW4[lane + 32], sW4[lane + 32]);

    float2* shw = sh[w];
    const uint2*  embh2 = (const uint2*)g_emb_h;   // lane owns halves 4l..4l+3
    const float4* wrow2 = (const float4*)(sW2 + lane * 132);
    const float4* wrow3 = (const float4*)(sW3 + lane * 68);

    const int gwarp = blockIdx.x * WPB + w;
    const int row0  = gwarp * R;
    if (row0 >= nrows) return;
    const bool full = (row0 + R <= nrows);

    int xi[R];
    #pragma unroll
    for (int r = 0; r < R; ++r) {
        int row = row0 + r;
        xi[r] = (full || row < nrows) ? x[row * 32 + lane] : 0;
    }

    // ---- Gather-sum, one row-pair at a time: only 8 acc regs live, store the
    //      pair immediately (STS is fire-and-forget). unroll 4 keeps MLP ~8.
    #pragma unroll
    for (int q = 0; q < NPAIR; ++q) {
        float2 a01_0 = make_float2(0.f, 0.f), a23_0 = make_float2(0.f, 0.f);
        float2 a01_1 = make_float2(0.f, 0.f), a23_1 = make_float2(0.f, 0.f);

        #pragma unroll 4
        for (int j = 0; j < 29; ++j) {
            int i0 = __shfl_sync(0xffffffffu, xi[2 * q],     j);
            int i1 = __shfl_sync(0xffffffffu, xi[2 * q + 1], j);
            uint2 v0 = __ldg(embh2 + (size_t)i0 * 32 + lane);
            uint2 v1 = __ldg(embh2 + (size_t)i1 * 32 + lane);
            a01_0 = fadd2(a01_0, __half22float2(*(const __half2*)&v0.x));
            a23_0 = fadd2(a23_0, __half22float2(*(const __half2*)&v0.y));
            a01_1 = fadd2(a01_1, __half22float2(*(const __half2*)&v1.x));
            a23_1 = fadd2(a23_1, __half22float2(*(const __half2*)&v1.y));
        }

        // ReLU + pair-interleave: {h_r0[k], h_r1[k]} pairs, lane owns k=4l..4l+3.
        float4 s0 = make_float4(fmaxf(a01_0.x, 0.f), fmaxf(a01_1.x, 0.f),
                                fmaxf(a01_0.y, 0.f), fmaxf(a01_1.y, 0.f));
        float4 s1 = make_float4(fmaxf(a23_0.x, 0.f), fmaxf(a23_1.x, 0.f),
                                fmaxf(a23_0.y, 0.f), fmaxf(a23_1.y, 0.f));
        float4* hq = (float4*)(shw + q * 128);
        hq[2 * lane]     = s0;   // k = 4l, 4l+1
        hq[2 * lane + 1] = s1;   // k = 4l+2, 4l+3
    }
    __syncwarp();

    // ---- Layer 2: packed over row-pairs; weights amortized over 8 rows ----
    float2 h2p[NPAIR];
    #pragma unroll
    for (int q = 0; q < NPAIR; ++q) h2p[q] = make_float2(bias2, bias2);

    #pragma unroll 8
    for (int c = 0; c < 32; ++c) {              // k = 4c..4c+3
        float4 wv = wrow2[c];
        float2 wxx = make_float2(wv.x, wv.x);
        float2 wyy = make_float2(wv.y, wv.y);
        float2 wzz = make_float2(wv.z, wv.z);
        float2 www = make_float2(wv.w, wv.w);
        #pragma unroll
        for (int q = 0; q < NPAIR; ++q) {
            const float4* hq = (const float4*)(shw + q * 128);
            float4 p0 = hq[2 * c];              // {k=4c, 4c+1} broadcast
            float4 p1 = hq[2 * c + 1];          // {k=4c+2, 4c+3}
            h2p[q] = ffma2(wxx, make_float2(p0.x, p0.y), h2p[q]);
            h2p[q] = ffma2(wyy, make_float2(p0.z, p0.w), h2p[q]);
            h2p[q] = ffma2(wzz, make_float2(p1.x, p1.y), h2p[q]);
            h2p[q] = ffma2(www, make_float2(p1.z, p1.w), h2p[q]);
        }
    }

    // ---- CReLU -> pair-interleaved a, reuse sh region ----
    __syncwarp();
    #pragma unroll
    for (int q = 0; q < NPAIR; ++q) {
        float2 alo = make_float2(fmaxf(h2p[q].x, 0.f), fmaxf(h2p[q].y, 0.f));
        float2 ahi = make_float2(fmaxf(-h2p[q].x, 0.f), fmaxf(-h2p[q].y, 0.f));
        shw[q * 64 + lane]      = alo;
        shw[q * 64 + lane + 32] = ahi;
    }
    __syncwarp();

    // ---- Layer 3 ----
    float2 h3p[NPAIR];
    #pragma unroll
    for (int q = 0; q < NPAIR; ++q) h3p[q] = make_float2(bias3, bias3);

    #pragma unroll 4
    for (int c = 0; c < 16; ++c) {
        float4 wv = wrow3[c];
        float2 wxx = make_float2(wv.x, wv.x);
        float2 wyy = make_float2(wv.y, wv.y);
        float2 wzz = make_float2(wv.z, wv.z);
        float2 www = make_float2(wv.w, wv.w);
        #pragma unroll
        for (int q = 0; q < NPAIR; ++q) {
            const float4* aq = (const float4*)(shw + q * 64);
            float4 p0 = aq[2 * c];
            float4 p1 = aq[2 * c + 1];
            h3p[q] = ffma2(wxx, make_float2(p0.x, p0.y), h3p[q]);
            h3p[q] = ffma2(wyy, make_float2(p0.z, p0.w), h3p[q]);
            h3p[q] = ffma2(wzz, make_float2(p1.x, p1.y), h3p[q]);
            h3p[q] = ffma2(www, make_float2(p1.z, p1.w), h3p[q]);
        }
    }

    // ---- Layer 4 + packed warp reduction ----
    float2 part[NPAIR];
    #pragma unroll
    for (int q = 0; q < NPAIR; ++q) {
        float2 blo = make_float2(fmaxf(h3p[q].x, 0.f), fmaxf(h3p[q].y, 0.f));
        float2 bhi = make_float2(fmaxf(-h3p[q].x, 0.f), fmaxf(-h3p[q].y, 0.f));
        float2 p = ffma2(w4hi2, bhi, make_float2(0.f, 0.f));
        p = ffma2(w4lo2, blo, p);
        #pragma unroll
        for (int off = 16; off; off >>= 1) {
            float2 o;
            o.x = __shfl_xor_sync(0xffffffffu, p.x, off);
            o.y = __shfl_xor_sync(0xffffffffu, p.y, off);
            p = fadd2(p, o);
        }
        part[q] = p;
    }

    if (lane == 0) {
        if (full) {
            *(float4*)(out + row0) =
                make_float4(part[0].x, part[0].y, part[1].x, part[1].y);
            *(float4*)(out + row0 + 4) =
                make_float4(part[2].x, part[2].y, part[3].x, part[3].y);
        } else {
            float pr[R] = {part[0].x, part[0].y, part[1].x, part[1].y,
                           part[2].x, part[2].y, part[3].x, part[3].y};
            for (int r = 0; r < R && row0 + r < nrows; ++r) out[row0 + r] = pr[r];
        }
    }
}

extern "C" void kernel_launch(void* const* d_in, const int* in_sizes, int n_in,
                              void* d_out, int out_size)
{
    const int*   x   = (const int*)  d_in[0];
    const float* emb = (const float*)d_in[1];
    const float* W2  = (const float*)d_in[2];
    const float* b2  = (const float*)d_in[3];
    const float* W3  = (const float*)d_in[4];
    const float* b3  = (const float*)d_in[5];
    const float* W4  = (const float*)d_in[6];
    float* out = (float*)d_out;

    int nemb  = in_sizes[1];
    int nrows = in_sizes[0] / 32;

    cvt_emb_kernel<<<(nemb + 511) / 512, 512>>>(emb, nemb);

    int ngroups = (nrows + R - 1) / R;
    int nblocks = (ngroups + WPB - 1) / WPB;
    silk_nnue_kernel<<<nblocks, THREADS>>>(x, W2, b2, W3, b3, W4, out, nrows);
}

// round 11
// speedup vs baseline: 2.4683x; 1.1717x over previous
#include <cuda_runtime.h>
#include <cuda_fp16.h>

#define WPB 4
#define THREADS (WPB * 32)
#define R 8
#define NPAIR (R / 2)

#define EMB_ELEMS (7424 * 128)
__device__ __half g_emb_h[EMB_ELEMS];   // fp16 repacked embedding table (1.9 MB)

__global__ void cvt_emb_kernel(const float* __restrict__ emb, int n)
{
    int i = blockIdx.x * blockDim.x + threadIdx.x;
    if (i < n) g_emb_h[i] = __float2half(emb[i]);
}

// Packed 2-wide fp32 ops (Blackwell f32x2 pipe; PTX-only).
__device__ __forceinline__ float2 ffma2(float2 a, float2 b, float2 c)
{
    float2 d;
    asm("{\n\t.reg .b64 ra,rb,rc,rd;\n\t"
        "mov.b64 ra,{%2,%3};\n\tmov.b64 rb,{%4,%5};\n\tmov.b64 rc,{%6,%7};\n\t"
        "fma.rn.f32x2 rd, ra, rb, rc;\n\t"
        "mov.b64 {%0,%1}, rd;\n\t}"
        : "=f"(d.x), "=f"(d.y)
        : "f"(a.x), "f"(a.y), "f"(b.x), "f"(b.y), "f"(c.x), "f"(c.y));
    return d;
}
__device__ __forceinline__ float2 fadd2(float2 a, float2 b)
{
    float2 d;
    asm("{\n\t.reg .b64 ra,rb,rd;\n\t"
        "mov.b64 ra,{%2,%3};\n\tmov.b64 rb,{%4,%5};\n\t"
        "add.rn.f32x2 rd, ra, rb;\n\t"
        "mov.b64 {%0,%1}, rd;\n\t}"
        : "=f"(d.x), "=f"(d.y)
        : "f"(a.x), "f"(a.y), "f"(b.x), "f"(b.y));
    return d;
}

__global__ __launch_bounds__(THREADS)
void silk_nnue_kernel(const int*   __restrict__ x,
                      const float* __restrict__ W2,
                      const float* __restrict__ b2,
                      const float* __restrict__ W3,
                      const float* __restrict__ b3,
                      const float* __restrict__ W4,
                      float*       __restrict__ out,
                      int nrows)
{
    // fp32 weights, padded stride 132/68 floats => conflict-free LDS.128 sweeps.
    __shared__ float  sW2[32 * 132];
    __shared__ float  sW3[32 * 68];
    __shared__ float  sb2[32], sb3[32], sW4[64];
    // Per-warp pair-interleaved fp32 activations: (q,k) = {row2q[k], row2q+1[k]}
    __shared__ float2 sh[WPB][NPAIR * 128];

    const int tid = threadIdx.x;

    for (int i = tid; i < 32 * 128; i += THREADS)
        sW2[(i >> 7) * 132 + (i & 127)] = W2[i];
    for (int i = tid; i < 32 * 64; i += THREADS)
        sW3[(i >> 6) * 68 + (i & 63)] = W3[i];
    if (tid < 32)       sb2[tid]      = b2[tid];
    else if (tid < 64)  sb3[tid - 32] = b3[tid - 32];
    if (tid < 64)       sW4[tid]      = W4[tid];
    __syncthreads();

    const int lane = tid & 31;
    const int w    = tid >> 5;

    const float bias2 = sb2[lane];
    const float bias3 = sb3[lane];
    const float2 w4lo2 = make_float2(sW4[lane],      sW4[lane]);
    const float2 w4hi2 = make_float2(sW4[lane + 32], sW4[lane + 32]);

    float2* shw = sh[w];
    // Two loop-invariant per-lane base pointers. Lane owns halves {2l, 2l+1}
    // (line 0) and {64+2l, 64+2l+1} (line 1). Each gather load then compiles
    // to one IMAD.WIDE(idx, 256, base) + LDG.32 — single-wavefront loads at
    // the 1.0 cyc/wf cross-LDG rate (vs 2x2.07 within-LDG replay of LDG.64).
    const unsigned* __restrict__ emb_lo = ((const unsigned*)g_emb_h) + lane;
    const unsigned* __restrict__ emb_hi = ((const unsigned*)g_emb_h) + lane + 32;
    const float4* wrow2 = (const float4*)(sW2 + lane * 132);
    const float4* wrow3 = (const float4*)(sW3 + lane * 68);

    const int gwarp = blockIdx.x * WPB + w;
    const int row0  = gwarp * R;
    if (row0 >= nrows) return;
    const bool full = (row0 + R <= nrows);

    int xi[R];
    #pragma unroll
    for (int r = 0; r < R; ++r) {
        int row = row0 + r;
        xi[r] = (full || row < nrows) ? x[row * 32 + lane] : 0;
    }

    // ---- Gather-sum: 29*R*2 independent single-line LDG.32, max MLP ----
    float2 acc01[R], acc23[R];
    #pragma unroll
    for (int r = 0; r < R; ++r) {
        acc01[r] = make_float2(0.f, 0.f);
        acc23[r] = make_float2(0.f, 0.f);
    }

    for (int j = 0; j < 29; ++j) {
        #pragma unroll
        for (int r = 0; r < R; ++r) {
            int idx = __shfl_sync(0xffffffffu, xi[r], j);
            size_t t = (size_t)idx * 64;          // row offset in uint units
            unsigned v0 = __ldg(emb_lo + t);      // IMAD.WIDE + LDG.32 (line 0)
            unsigned v1 = __ldg(emb_hi + t);      // IMAD.WIDE + LDG.32 (line 1)
            acc01[r] = fadd2(acc01[r], __half22float2(*(const __half2*)&v0));
            acc23[r] = fadd2(acc23[r], __half22float2(*(const __half2*)&v1));
        }
    }

    // ReLU + pair-interleaved store at absolute k positions (two STS.128, conflict-free).
    #pragma unroll
    for (int q = 0; q < NPAIR; ++q) {
        const int r0 = 2 * q, r1 = 2 * q + 1;
        float4 s0 = make_float4(fmaxf(acc01[r0].x, 0.f), fmaxf(acc01[r1].x, 0.f),
                                fmaxf(acc01[r0].y, 0.f), fmaxf(acc01[r1].y, 0.f));
        float4 s1 = make_float4(fmaxf(acc23[r0].x, 0.f), fmaxf(acc23[r1].x, 0.f),
                                fmaxf(acc23[r0].y, 0.f), fmaxf(acc23[r1].y, 0.f));
        *(float4*)(shw + q * 128 + 2 * lane)      = s0;   // k = 2l, 2l+1
        *(float4*)(shw + q * 128 + 64 + 2 * lane) = s1;   // k = 64+2l, 64+2l+1
    }
    __syncwarp();

    // ---- Layer 2: packed over row-pairs; weights amortized over 8 rows ----
    float2 h2p[NPAIR];
    #pragma unroll
    for (int q = 0; q < NPAIR; ++q) h2p[q] = make_float2(bias2, bias2);

    #pragma unroll 8
    for (int c = 0; c < 32; ++c) {              // k = 4c..4c+3
        float4 wv = wrow2[c];
        float2 wxx = make_float2(wv.x, wv.x);
        float2 wyy = make_float2(wv.y, wv.y);
        float2 wzz = make_float2(wv.z, wv.z);
        float2 www = make_float2(wv.w, wv.w);
        #pragma unroll
        for (int q = 0; q < NPAIR; ++q) {
            const float4* hq = (const float4*)(shw + q * 128);
            float4 p0 = hq[2 * c];              // {k=4c, 4c+1} broadcast
            float4 p1 = hq[2 * c + 1];          // {k=4c+2, 4c+3}
            h2p[q] = ffma2(wxx, make_float2(p0.x, p0.y), h2p[q]);
            h2p[q] = ffma2(wyy, make_float2(p0.z, p0.w), h2p[q]);
            h2p[q] = ffma2(wzz, make_float2(p1.x, p1.y), h2p[q]);
            h2p[q] = ffma2(www, make_float2(p1.z, p1.w), h2p[q]);
        }
    }

    // ---- CReLU -> pair-interleaved a, reuse sh region ----
    __syncwarp();
    #pragma unroll
    for (int q = 0; q < NPAIR; ++q) {
        float2 alo = make_float2(fmaxf(h2p[q].x, 0.f), fmaxf(h2p[q].y, 0.f));
        float2 ahi = make_float2(fmaxf(-h2p[q].x, 0.f), fmaxf(-h2p[q].y, 0.f));
        shw[q * 64 + lane]      = alo;
        shw[q * 64 + lane + 32] = ahi;
    }
    __syncwarp();

    // ---- Layer 3 ----
    float2 h3p[NPAIR];
    #pragma unroll
    for (int q = 0; q < NPAIR; ++q) h3p[q] = make_float2(bias3, bias3);

    #pragma unroll 4
    for (int c = 0; c < 16; ++c) {
        float4 wv = wrow3[c];
        float2 wxx = make_float2(wv.x, wv.x);
        float2 wyy = make_float2(wv.y, wv.y);
        float2 wzz = make_float2(wv.z, wv.z);
        float2 www = make_float2(wv.w, wv.w);
        #pragma unroll
        for (int q = 0; q < NPAIR; ++q) {
            const float4* aq = (const float4*)(shw + q * 64);
            float4 p0 = aq[2 * c];
            float4 p1 = aq[2 * c + 1];
            h3p[q] = ffma2(wxx, make_float2(p0.x, p0.y), h3p[q]);
            h3p[q] = ffma2(wyy, make_float2(p0.z, p0.w), h3p[q]);
            h3p[q] = ffma2(wzz, make_float2(p1.x, p1.y), h3p[q]);
            h3p[q] = ffma2(www, make_float2(p1.z, p1.w), h3p[q]);
        }
    }

    // ---- Layer 4 + packed warp reduction ----
    float2 part[NPAIR];
    #pragma unroll
    for (int q = 0; q < NPAIR; ++q) {
        float2 blo = make_float2(fmaxf(h3p[q].x, 0.f), fmaxf(h3p[q].y, 0.f));
        float2 bhi = make_float2(fmaxf(-h3p[q].x, 0.f), fmaxf(-h3p[q].y, 0.f));
        float2 p = ffma2(w4hi2, bhi, make_float2(0.f, 0.f));
        p = ffma2(w4lo2, blo, p);
        #pragma unroll
        for (int off = 16; off; off >>= 1) {
            float2 o;
            o.x = __shfl_xor_sync(0xffffffffu, p.x, off);
            o.y = __shfl_xor_sync(0xffffffffu, p.y, off);
            p = fadd2(p, o);
        }
        part[q] = p;
    }

    if (lane == 0) {
        if (full) {
            *(float4*)(out + row0) =
                make_float4(part[0].x, part[0].y, part[1].x, part[1].y);
            *(float4*)(out + row0 + 4) =
                make_float4(part[2].x, part[2].y, part[3].x, part[3].y);
        } else {
            float pr[R] = {part[0].x, part[0].y, part[1].x, part[1].y,
                           part[2].x, part[2].y, part[3].x, part[3].y};
            for (int r = 0; r < R && row0 + r < nrows; ++r) out[row0 + r] = pr[r];
        }
    }
}

extern "C" void kernel_launch(void* const* d_in, const int* in_sizes, int n_in,
                              void* d_out, int out_size)
{
    const int*   x   = (const int*)  d_in[0];
    const float* emb = (const float*)d_in[1];
    const float* W2  = (const float*)d_in[2];
    const float* b2  = (const float*)d_in[3];
    const float* W3  = (const float*)d_in[4];
    const float* b3  = (const float*)d_in[5];
    const float* W4  = (const float*)d_in[6];
    float* out = (float*)d_out;

    int nemb  = in_sizes[1];
    int nrows = in_sizes[0] / 32;

    cvt_emb_kernel<<<(nemb + 511) / 512, 512>>>(emb, nemb);

    int ngroups = (nrows + R - 1) / R;
    int nblocks = (ngroups + WPB - 1) / WPB;
    silk_nnue_kernel<<<nblocks, THREADS>>>(x, W2, b2, W3, b3, W4, out, nrows);
}